// round 4
// baseline (speedup 1.0000x reference)
#include <cuda_runtime.h>
#include <cuda_fp16.h>
#include <stdint.h>

#define N_NODES_MAX 100000
#define IN_FEAT 64
#define OUT_FEAT 64
#define NUM_BASES 4
#define NUM_RELS 8
#define P2_COLS (NUM_RELS * OUT_FEAT)   // 512 halves per node

// Scratch: per-(node, relation) combined projections, fp16 [N, 8, 64] (~102.4 MB)
__device__ __half g_proj2[(size_t)N_NODES_MAX * P2_COLS];

// ---------------------------------------------------------------------------
// Kernel A: fused GEMM + basis->relation combination
//   For each node tile (64 rows):
//     basis b: acc = feat_tile @ V_b            (64x64x64)
//              rcomb[r] += w_comp[r,b] * acc    (8 rels, in registers)
//     -> g_proj2[n, r, :] as fp16
//     loop:    out[n,:] = h_bias + feat_tile @ loop_w   (fp32)
// 512 threads: thread owns 2 rows x 4 cols.
// ---------------------------------------------------------------------------
__global__ __launch_bounds__(512, 1) void rgcn_gemm_kernel(
    const float* __restrict__ feat,      // [N, 64]
    const float* __restrict__ weight,    // [4, 64, 64]
    const float* __restrict__ w_comp,    // [8, 4]
    const float* __restrict__ loop_w,    // [64, 64]
    const float* __restrict__ h_bias,    // [64]
    float* __restrict__ out,             // [N, 64]
    int n_nodes)
{
    __shared__ __align__(16) float sA[IN_FEAT][66];  // transposed feat tile sA[k][r]
    __shared__ __align__(16) float sB[IN_FEAT][64];  // weight tile sB[k][c]
    __shared__ float sWC[NUM_RELS][NUM_BASES];

    const int tid = threadIdx.x;
    const int row0 = blockIdx.x * 64;

    if (tid < NUM_RELS * NUM_BASES) sWC[tid >> 2][tid & 3] = w_comp[tid];

    // Load 64x64 feat tile, transposed into sA[k][r]
    #pragma unroll
    for (int i = tid; i < 64 * 64; i += 512) {
        int r = i >> 6;
        int k = i & 63;
        int row = row0 + r;
        sA[k][r] = (row < n_nodes) ? feat[(size_t)row * IN_FEAT + k] : 0.0f;
    }

    const int tx = tid & 15;   // col group: 4 cols
    const int ty = tid >> 4;   // row group: 2 rows (0..31)

    float rcomb[NUM_RELS][2][4];
    #pragma unroll
    for (int r = 0; r < NUM_RELS; ++r)
        #pragma unroll
        for (int i = 0; i < 2; ++i)
            #pragma unroll
            for (int j = 0; j < 4; ++j)
                rcomb[r][i][j] = 0.0f;

    for (int b = 0; b < NUM_BASES; ++b) {
        __syncthreads();
        #pragma unroll
        for (int i = tid; i < 64 * 64; i += 512) {
            int k = i >> 6;
            int c = i & 63;
            sB[k][c] = weight[((size_t)b * 64 + k) * 64 + c];
        }
        __syncthreads();

        float acc[2][4] = {};
        #pragma unroll
        for (int k = 0; k < 64; ++k) {
            float2 a = *(const float2*)&sA[k][ty * 2];
            float4 w = *(const float4*)&sB[k][tx * 4];
            acc[0][0] += a.x * w.x; acc[0][1] += a.x * w.y;
            acc[0][2] += a.x * w.z; acc[0][3] += a.x * w.w;
            acc[1][0] += a.y * w.x; acc[1][1] += a.y * w.y;
            acc[1][2] += a.y * w.z; acc[1][3] += a.y * w.w;
        }

        #pragma unroll
        for (int r = 0; r < NUM_RELS; ++r) {
            float c = sWC[r][b];
            #pragma unroll
            for (int i = 0; i < 2; ++i)
                #pragma unroll
                for (int j = 0; j < 4; ++j)
                    rcomb[r][i][j] += c * acc[i][j];
        }
    }

    // Store combined projections as fp16
    #pragma unroll
    for (int i = 0; i < 2; ++i) {
        int row = row0 + ty * 2 + i;
        if (row < n_nodes) {
            #pragma unroll
            for (int r = 0; r < NUM_RELS; ++r) {
                __half2 h0 = __floats2half2_rn(rcomb[r][i][0], rcomb[r][i][1]);
                __half2 h1 = __floats2half2_rn(rcomb[r][i][2], rcomb[r][i][3]);
                uint2 v;
                v.x = *reinterpret_cast<unsigned int*>(&h0);
                v.y = *reinterpret_cast<unsigned int*>(&h1);
                *reinterpret_cast<uint2*>(
                    &g_proj2[(size_t)row * P2_COLS + r * OUT_FEAT + tx * 4]) = v;
            }
        }
    }

    // Self-loop tile: out = h_bias + feat @ loop_w
    __syncthreads();
    #pragma unroll
    for (int i = tid; i < 64 * 64; i += 512) {
        int k = i >> 6;
        int c = i & 63;
        sB[k][c] = loop_w[(size_t)k * 64 + c];
    }
    __syncthreads();

    float acc[2][4] = {};
    #pragma unroll
    for (int k = 0; k < 64; ++k) {
        float2 a = *(const float2*)&sA[k][ty * 2];
        float4 w = *(const float4*)&sB[k][tx * 4];
        acc[0][0] += a.x * w.x; acc[0][1] += a.x * w.y;
        acc[0][2] += a.x * w.z; acc[0][3] += a.x * w.w;
        acc[1][0] += a.y * w.x; acc[1][1] += a.y * w.y;
        acc[1][2] += a.y * w.z; acc[1][3] += a.y * w.w;
    }

    float b0 = h_bias[tx * 4 + 0];
    float b1 = h_bias[tx * 4 + 1];
    float b2 = h_bias[tx * 4 + 2];
    float b3 = h_bias[tx * 4 + 3];
    #pragma unroll
    for (int i = 0; i < 2; ++i) {
        int row = row0 + ty * 2 + i;
        if (row < n_nodes) {
            float4 v = make_float4(acc[i][0] + b0, acc[i][1] + b1,
                                   acc[i][2] + b2, acc[i][3] + b3);
            *(float4*)&out[(size_t)row * OUT_FEAT + tx * 4] = v;
        }
    }
}

// ---------------------------------------------------------------------------
// Kernel B: per-edge gather/scale/scatter
//   msg = proj2[src, etype, :] * norm          (fp16 gather, 128 B/edge)
//   out[dst, :] += msg                         (red.global.add.v4.f32)
// 16 threads per edge, each owning 4 contiguous output features.
// ---------------------------------------------------------------------------
__global__ __launch_bounds__(256) void rgcn_edge_kernel(
    const int* __restrict__ src,
    const int* __restrict__ dst,
    const int* __restrict__ etypes,
    const float* __restrict__ norm,      // [E, 1]
    float* __restrict__ out,             // [N, 64]
    int n_edges)
{
    int idx = blockIdx.x * blockDim.x + threadIdx.x;
    int e = idx >> 4;
    int lane = idx & 15;
    if (e >= n_edges) return;

    int s = __ldg(&src[e]);
    int d = __ldg(&dst[e]);
    int t = __ldg(&etypes[e]);
    float nm = __ldg(&norm[e]);

    const __half* p = g_proj2 + ((size_t)s * P2_COLS + t * OUT_FEAT + lane * 4);
    uint2 raw = __ldg(reinterpret_cast<const uint2*>(p));
    __half2 h0 = *reinterpret_cast<__half2*>(&raw.x);
    __half2 h1 = *reinterpret_cast<__half2*>(&raw.y);
    float2 f0 = __half22float2(h0);
    float2 f1 = __half22float2(h1);

    float4 m = make_float4(f0.x * nm, f0.y * nm, f1.x * nm, f1.y * nm);

    float* o = out + (size_t)d * OUT_FEAT + lane * 4;
    asm volatile("red.global.add.v4.f32 [%0], {%1, %2, %3, %4};"
                 :: "l"(o), "f"(m.x), "f"(m.y), "f"(m.z), "f"(m.w)
                 : "memory");
}

// ---------------------------------------------------------------------------
extern "C" void kernel_launch(void* const* d_in, const int* in_sizes, int n_in,
                              void* d_out, int out_size)
{
    const float* feat    = (const float*)d_in[0];
    const int*   src     = (const int*)d_in[1];
    const int*   dst     = (const int*)d_in[2];
    const int*   etypes  = (const int*)d_in[3];
    const float* norm    = (const float*)d_in[4];
    const float* weight  = (const float*)d_in[5];
    const float* w_comp  = (const float*)d_in[6];
    const float* h_bias  = (const float*)d_in[7];
    const float* loop_w  = (const float*)d_in[8];
    float*       out     = (float*)d_out;

    int n_nodes = in_sizes[0] / IN_FEAT;
    int n_edges = in_sizes[1];

    // Phase 1: combined projections (fp16) + self-loop/bias init of out (fp32)
    int gemm_blocks = (n_nodes + 63) / 64;
    rgcn_gemm_kernel<<<gemm_blocks, 512>>>(feat, weight, w_comp, loop_w, h_bias,
                                           out, n_nodes);

    // Phase 2: edge message + aggregation
    long long total_threads = (long long)n_edges * 16;
    int edge_blocks = (int)((total_threads + 255) / 256);
    rgcn_edge_kernel<<<edge_blocks, 256>>>(src, dst, etypes, norm, out, n_edges);
}

// round 5
// speedup vs baseline: 1.6748x; 1.6748x over previous
#include <cuda_runtime.h>
#include <cuda_fp16.h>
#include <stdint.h>

#define N_NODES_MAX 100000
#define IN_FEAT 64
#define OUT_FEAT 64
#define NUM_BASES 4
#define NUM_RELS 8
#define P2_COLS (NUM_RELS * OUT_FEAT)      // 512
#define WCAT_COLS (P2_COLS + OUT_FEAT)     // 576 (cols 512..575 = self-loop)

// Scratch: per-(node, relation) combined projections, fp16 [N, 8, 64] (~102.4 MB)
__device__ __half g_proj2[(size_t)N_NODES_MAX * P2_COLS];
// Combined weight matrix [64, 576] fp16
__device__ __half g_wcat[IN_FEAT * WCAT_COLS];

// ---------------------------------------------------------------------------
// Kernel 0: build Wcat (tiny)
//   n < 512:  Wcat[k, n] = sum_b w_comp[n>>6, b] * weight[b, k, n&63]
//   n >= 512: Wcat[k, n] = loop_w[k, n-512]
// ---------------------------------------------------------------------------
__global__ void wcat_kernel(const float* __restrict__ weight,
                            const float* __restrict__ w_comp,
                            const float* __restrict__ loop_w)
{
    int idx = blockIdx.x * blockDim.x + threadIdx.x;
    if (idx >= IN_FEAT * WCAT_COLS) return;
    int k = idx / WCAT_COLS;
    int n = idx % WCAT_COLS;
    float v;
    if (n < P2_COLS) {
        int r = n >> 6, o = n & 63;
        v = 0.0f;
        #pragma unroll
        for (int b = 0; b < NUM_BASES; ++b)
            v += w_comp[r * NUM_BASES + b] * weight[((size_t)b * 64 + k) * 64 + o];
    } else {
        v = loop_w[(size_t)k * 64 + (n - P2_COLS)];
    }
    g_wcat[idx] = __float2half_rn(v);
}

// ---------------------------------------------------------------------------
// mma.sync helpers
// ---------------------------------------------------------------------------
__device__ __forceinline__ uint32_t smem_u32(const void* p) {
    return (uint32_t)__cvta_generic_to_shared(p);
}

#define LDSM_X4(r0, r1, r2, r3, addr)                                          \
    asm volatile("ldmatrix.sync.aligned.m8n8.x4.shared.b16 {%0,%1,%2,%3}, [%4];" \
                 : "=r"(r0), "=r"(r1), "=r"(r2), "=r"(r3) : "r"(addr))

#define LDSM_X4_T(r0, r1, r2, r3, addr)                                        \
    asm volatile("ldmatrix.sync.aligned.m8n8.x4.trans.shared.b16 {%0,%1,%2,%3}, [%4];" \
                 : "=r"(r0), "=r"(r1), "=r"(r2), "=r"(r3) : "r"(addr))

#define MMA_16816(d, a, b)                                                     \
    asm volatile("mma.sync.aligned.m16n8k16.row.col.f32.f16.f16.f32 "          \
                 "{%0,%1,%2,%3}, {%4,%5,%6,%7}, {%8,%9}, {%0,%1,%2,%3};"       \
                 : "+f"(d[0]), "+f"(d[1]), "+f"(d[2]), "+f"(d[3])              \
                 : "r"(a[0]), "r"(a[1]), "r"(a[2]), "r"(a[3]),                 \
                   "r"(b[0]), "r"(b[1]))

// ---------------------------------------------------------------------------
// Kernel A: proj2 (fp16) + out-init (fp32) via HMMA
//   [128-row tile, 64] fp16 @ [64, 576] fp16 -> cols 0..511 fp16 proj2,
//                                               cols 512..575 fp32 out + bias
// 256 threads = 8 warps in 4x2 grid; warp tile 32x32.
// ---------------------------------------------------------------------------
#define SA_STRIDE 72   // halves; 144B row stride -> conflict-free ldmatrix
#define SB_STRIDE 72

__global__ __launch_bounds__(256) void rgcn_mma_kernel(
    const float* __restrict__ feat,      // [N, 64]
    const float* __restrict__ h_bias,    // [64]
    float* __restrict__ out,             // [N, 64]
    int n_nodes)
{
    __shared__ __align__(16) __half sA[128 * SA_STRIDE];
    __shared__ __align__(16) __half sB[64 * SB_STRIDE];

    const int tid = threadIdx.x;
    const int row0 = blockIdx.x * 128;

    // Load A tile (128 x 64), fp32 -> fp16
    #pragma unroll
    for (int i = tid; i < 128 * 32; i += 256) {
        int r = i >> 5;          // row in tile
        int cp = i & 31;         // column pair
        int row = row0 + r;
        float2 f = (row < n_nodes)
                     ? *(const float2*)&feat[(size_t)row * IN_FEAT + cp * 2]
                     : make_float2(0.0f, 0.0f);
        *(__half2*)&sA[r * SA_STRIDE + cp * 2] = __floats2half2_rn(f.x, f.y);
    }

    const int warp = tid >> 5;
    const int lane = tid & 31;
    const int wr = warp >> 1;    // 0..3: rows wr*32
    const int wc = warp & 1;     // 0..1: cols wc*32 (within 64-col pass)

    // ldmatrix source addresses (lane-dependent parts precomputed)
    const int lrow = lane & 15;
    const int lcol = (lane >> 4) << 3;

    const int g   = lane >> 2;   // C-fragment row group
    const int tig = lane & 3;    // C-fragment col pair

    for (int cp = 0; cp < 9; ++cp) {
        __syncthreads();   // protects sB reuse + (first iter) A load
        // Load B slice: g_wcat[k][cp*64 + c], 64 x 64
        #pragma unroll
        for (int i = tid; i < 64 * 32; i += 256) {
            int r = i >> 5;
            int c2 = i & 31;
            *(__half2*)&sB[r * SB_STRIDE + c2 * 2] =
                *(const __half2*)&g_wcat[(size_t)r * WCAT_COLS + cp * 64 + c2 * 2];
        }
        __syncthreads();

        float acc[2][4][4];
        #pragma unroll
        for (int mi = 0; mi < 2; ++mi)
            #pragma unroll
            for (int nj = 0; nj < 4; ++nj)
                #pragma unroll
                for (int q = 0; q < 4; ++q)
                    acc[mi][nj][q] = 0.0f;

        #pragma unroll
        for (int ks = 0; ks < 4; ++ks) {
            uint32_t a[2][4];
            #pragma unroll
            for (int mi = 0; mi < 2; ++mi) {
                const __half* p = &sA[(wr * 32 + mi * 16 + lrow) * SA_STRIDE
                                      + ks * 16 + lcol];
                LDSM_X4(a[mi][0], a[mi][1], a[mi][2], a[mi][3], smem_u32(p));
            }
            uint32_t b[4][2];
            #pragma unroll
            for (int np = 0; np < 2; ++np) {   // each covers two n8 tiles
                const __half* p = &sB[(ks * 16 + lrow) * SB_STRIDE
                                      + wc * 32 + np * 16 + lcol];
                uint32_t r0, r1, r2, r3;
                LDSM_X4_T(r0, r1, r2, r3, smem_u32(p));
                b[np * 2 + 0][0] = r0; b[np * 2 + 0][1] = r1;
                b[np * 2 + 1][0] = r2; b[np * 2 + 1][1] = r3;
            }
            #pragma unroll
            for (int mi = 0; mi < 2; ++mi)
                #pragma unroll
                for (int nj = 0; nj < 4; ++nj)
                    MMA_16816(acc[mi][nj], a[mi], b[nj]);
        }

        // Epilogue
        if (cp < 8) {
            #pragma unroll
            for (int mi = 0; mi < 2; ++mi) {
                int ra = row0 + wr * 32 + mi * 16 + g;
                int rb = ra + 8;
                #pragma unroll
                for (int nj = 0; nj < 4; ++nj) {
                    int col = cp * 64 + wc * 32 + nj * 8 + tig * 2;
                    if (ra < n_nodes)
                        *(__half2*)&g_proj2[(size_t)ra * P2_COLS + col] =
                            __floats2half2_rn(acc[mi][nj][0], acc[mi][nj][1]);
                    if (rb < n_nodes)
                        *(__half2*)&g_proj2[(size_t)rb * P2_COLS + col] =
                            __floats2half2_rn(acc[mi][nj][2], acc[mi][nj][3]);
                }
            }
        } else {
            #pragma unroll
            for (int mi = 0; mi < 2; ++mi) {
                int ra = row0 + wr * 32 + mi * 16 + g;
                int rb = ra + 8;
                #pragma unroll
                for (int nj = 0; nj < 4; ++nj) {
                    int col = wc * 32 + nj * 8 + tig * 2;
                    float b0 = h_bias[col];
                    float b1 = h_bias[col + 1];
                    if (ra < n_nodes) {
                        out[(size_t)ra * OUT_FEAT + col]     = acc[mi][nj][0] + b0;
                        out[(size_t)ra * OUT_FEAT + col + 1] = acc[mi][nj][1] + b1;
                    }
                    if (rb < n_nodes) {
                        out[(size_t)rb * OUT_FEAT + col]     = acc[mi][nj][2] + b0;
                        out[(size_t)rb * OUT_FEAT + col + 1] = acc[mi][nj][3] + b1;
                    }
                }
            }
        }
    }
}

// ---------------------------------------------------------------------------
// Kernel B: per-edge gather/scale/scatter  (UNCHANGED from R4 — proven)
//   msg = proj2[src, etype, :] * norm ; out[dst, :] += msg (red.global.add.v4)
// ---------------------------------------------------------------------------
__global__ __launch_bounds__(256) void rgcn_edge_kernel(
    const int* __restrict__ src,
    const int* __restrict__ dst,
    const int* __restrict__ etypes,
    const float* __restrict__ norm,      // [E, 1]
    float* __restrict__ out,             // [N, 64]
    int n_edges)
{
    int idx = blockIdx.x * blockDim.x + threadIdx.x;
    int e = idx >> 4;
    int lane = idx & 15;
    if (e >= n_edges) return;

    int s = __ldg(&src[e]);
    int d = __ldg(&dst[e]);
    int t = __ldg(&etypes[e]);
    float nm = __ldg(&norm[e]);

    const __half* p = g_proj2 + ((size_t)s * P2_COLS + t * OUT_FEAT + lane * 4);
    uint2 raw = __ldg(reinterpret_cast<const uint2*>(p));
    __half2 h0 = *reinterpret_cast<__half2*>(&raw.x);
    __half2 h1 = *reinterpret_cast<__half2*>(&raw.y);
    float2 f0 = __half22float2(h0);
    float2 f1 = __half22float2(h1);

    float4 m = make_float4(f0.x * nm, f0.y * nm, f1.x * nm, f1.y * nm);

    float* o = out + (size_t)d * OUT_FEAT + lane * 4;
    asm volatile("red.global.add.v4.f32 [%0], {%1, %2, %3, %4};"
                 :: "l"(o), "f"(m.x), "f"(m.y), "f"(m.z), "f"(m.w)
                 : "memory");
}

// ---------------------------------------------------------------------------
extern "C" void kernel_launch(void* const* d_in, const int* in_sizes, int n_in,
                              void* d_out, int out_size)
{
    const float* feat    = (const float*)d_in[0];
    const int*   src     = (const int*)d_in[1];
    const int*   dst     = (const int*)d_in[2];
    const int*   etypes  = (const int*)d_in[3];
    const float* norm    = (const float*)d_in[4];
    const float* weight  = (const float*)d_in[5];
    const float* w_comp  = (const float*)d_in[6];
    const float* h_bias  = (const float*)d_in[7];
    const float* loop_w  = (const float*)d_in[8];
    float*       out     = (float*)d_out;

    int n_nodes = in_sizes[0] / IN_FEAT;
    int n_edges = in_sizes[1];

    // Phase 0: combined weight matrix (fp16)
    wcat_kernel<<<(IN_FEAT * WCAT_COLS + 255) / 256, 256>>>(weight, w_comp, loop_w);

    // Phase 1: HMMA GEMM -> proj2 (fp16) + out init (fp32)
    int gemm_blocks = (n_nodes + 127) / 128;
    rgcn_mma_kernel<<<gemm_blocks, 256>>>(feat, h_bias, out, n_nodes);

    // Phase 2: edge message + aggregation
    long long total_threads = (long long)n_edges * 16;
    int edge_blocks = (int)((total_threads + 255) / 256);
    rgcn_edge_kernel<<<edge_blocks, 256>>>(src, dst, etypes, norm, out, n_edges);
}